// round 3
// baseline (speedup 1.0000x reference)
#include <cuda_runtime.h>

#define BATCH    16
#define NROWS    25200
#define NCOLS    85
#define MAXDET   300
#define CTHRES   0.25f
#define NTHREADS 256
#define NWARPS   (NTHREADS / 32)     // 8
#define ROUNDS   4                   // rows per super-chunk = 1024
#define SUPER    (ROUNDS * NTHREADS) // 1024
#define SLICES   20                  // CTAs per image
#define SLOTS    (MAXDET / SLICES)   // 15 slots per CTA

__global__ __launch_bounds__(NTHREADS, 4)
void compact_kernel(const float* __restrict__ pred, float* __restrict__ out)
{
    __shared__ int s_order[MAXDET];
    __shared__ int s_cnt[ROUNDS * NWARPS];   // 32 ordered warp counts
    __shared__ int s_off[ROUNDS * NWARPS];
    __shared__ int s_total;

    const int b     = blockIdx.x / SLICES;
    const int slice = blockIdx.x % SLICES;
    const int tid   = threadIdx.x;
    const int lane  = tid & 31;
    const int warp  = tid >> 5;

    const int slice_lo = slice * SLOTS;
    const int slice_hi = slice_lo + SLOTS;
    const unsigned lanemask = (1u << lane) - 1u;

    const float* bpred = pred + (long long)b * NROWS * NCOLS;

    int base = 0;
    const int nsuper = (NROWS + SUPER - 1) / SUPER;   // 25

    for (int sc = 0; sc < nsuper; ++sc) {
        const int row0 = sc * SUPER;

        // One memory round: 4 independent conf loads per thread.
        bool m[ROUNDS];
        #pragma unroll
        for (int r = 0; r < ROUNDS; ++r) {
            int i = row0 + r * NTHREADS + tid;
            float conf = (i < NROWS) ? __ldg(&bpred[(long long)i * NCOLS + 4]) : 0.0f;
            m[r] = conf > CTHRES;
        }

        unsigned bal[ROUNDS];
        #pragma unroll
        for (int r = 0; r < ROUNDS; ++r)
            bal[r] = __ballot_sync(0xffffffffu, m[r]);

        if (lane == 0) {
            #pragma unroll
            for (int r = 0; r < ROUNDS; ++r)
                s_cnt[r * NWARPS + warp] = __popc(bal[r]);
        }
        __syncthreads();

        // warp 0 scans the 32 ordered warp counts (round-major = row order)
        if (warp == 0) {
            int v = s_cnt[lane];
            int inc = v;
            #pragma unroll
            for (int o = 1; o < 32; o <<= 1) {
                int u = __shfl_up_sync(0xffffffffu, inc, o);
                if (lane >= o) inc += u;
            }
            s_off[lane] = inc - v;
            if (lane == 31) s_total = inc;
        }
        __syncthreads();

        int total = s_total;
        #pragma unroll
        for (int r = 0; r < ROUNDS; ++r) {
            if (m[r]) {
                int rank = base + s_off[r * NWARPS + warp] + __popc(bal[r] & lanemask);
                if (rank < MAXDET)
                    s_order[rank] = row0 + r * NTHREADS + tid;
            }
        }
        base += total;
        if (base >= slice_hi) break;   // uniform exit
        __syncthreads();               // protect s_cnt/s_off reuse
    }
    __syncthreads();                   // s_order visible to all

    int cnt = base;
    if (cnt > MAXDET) cnt = MAXDET;

    float* bout = out + (long long)b * MAXDET * NCOLS + (long long)slice_lo * NCOLS;

    // Gather this CTA's slice: 15*85 = 1275 elements, 5 per thread, all
    // loads independent (MLP=5), coalesced stores.
    int   src_k[5];
    int   col_k[5];
    bool  ok_k[5];
    #pragma unroll
    for (int k = 0; k < 5; ++k) {
        int e    = k * NTHREADS + tid;
        int sl   = e / NCOLS;
        col_k[k] = e - sl * NCOLS;
        int slot = slice_lo + sl;
        ok_k[k]  = (e < SLOTS * NCOLS) && (slot < cnt);
        src_k[k] = ok_k[k] ? s_order[slot] : 0;
    }
    float v_k[5];
    #pragma unroll
    for (int k = 0; k < 5; ++k)
        v_k[k] = ok_k[k] ? __ldg(&bpred[(long long)src_k[k] * NCOLS + col_k[k]]) : 0.0f;
    #pragma unroll
    for (int k = 0; k < 5; ++k) {
        int e = k * NTHREADS + tid;
        if (e < SLOTS * NCOLS) bout[e] = v_k[k];
    }
}

extern "C" void kernel_launch(void* const* d_in, const int* in_sizes, int n_in,
                              void* d_out, int out_size)
{
    const float* pred = (const float*)d_in[0];
    float* out = (float*)d_out;
    compact_kernel<<<BATCH * SLICES, NTHREADS>>>(pred, out);
}

// round 4
// speedup vs baseline: 1.2963x; 1.2963x over previous
#include <cuda_runtime.h>

#define BATCH    16
#define NROWS    25200
#define NCOLS    85
#define MAXDET   300
#define CTHRES   0.25f
#define NTHREADS 512
#define NWARPS   (NTHREADS / 32)     // 16
#define SLICES   10                  // CTAs per image
#define SLOTS    (MAXDET / SLICES)   // 30 slots per CTA

__global__ __launch_bounds__(NTHREADS, 2)
void compact_kernel(const float* __restrict__ pred, float* __restrict__ out)
{
    __shared__ int s_order[MAXDET];
    __shared__ int s_cnt[NWARPS];
    __shared__ int s_off[NWARPS];
    __shared__ int s_total;

    const int b     = blockIdx.x / SLICES;
    const int slice = blockIdx.x % SLICES;
    const int tid   = threadIdx.x;
    const int lane  = tid & 31;
    const int warp  = tid >> 5;

    const int slice_lo = slice * SLOTS;
    const int slice_hi = slice_lo + SLOTS;
    const unsigned lanemask = (1u << lane) - 1u;

    const float* bpred = pred + (long long)b * NROWS * NCOLS;

    int base = 0;
    const int nchunks = (NROWS + NTHREADS - 1) / NTHREADS;   // 50

    // Expected path: exactly ONE 512-row chunk (E[pass]=384 >= 300).
    for (int c = 0; c < nchunks; ++c) {
        int i = c * NTHREADS + tid;
        bool m = false;
        if (i < NROWS)
            m = __ldg(&bpred[(long long)i * NCOLS + 4]) > CTHRES;

        unsigned bal = __ballot_sync(0xffffffffu, m);
        if (lane == 0) s_cnt[warp] = __popc(bal);
        __syncthreads();

        if (warp == 0) {
            int v = (lane < NWARPS) ? s_cnt[lane] : 0;
            int inc = v;
            #pragma unroll
            for (int o = 1; o < 32; o <<= 1) {
                int u = __shfl_up_sync(0xffffffffu, inc, o);
                if (lane >= o) inc += u;
            }
            if (lane < NWARPS) s_off[lane] = inc - v;
            if (lane == 31) s_total = inc;
        }
        __syncthreads();

        if (m) {
            int rank = base + s_off[warp] + __popc(bal & lanemask);
            if (rank < MAXDET) s_order[rank] = i;
        }
        base += s_total;
        if (base >= slice_hi) break;    // uniform across CTA
        __syncthreads();                // protect s_cnt/s_off reuse
    }
    __syncthreads();                    // s_order visible

    int cnt = base;
    if (cnt > MAXDET) cnt = MAXDET;

    float* bout = out + (long long)b * MAXDET * NCOLS + (long long)slice_lo * NCOLS;

    // Gather this CTA's slice: 30*85 = 2550 elements, ~5 per thread,
    // loads independent (MLP=5), coalesced stores.
    const int NG = (SLOTS * NCOLS + NTHREADS - 1) / NTHREADS;   // 5
    int  src_k[NG];
    int  col_k[NG];
    bool ok_k[NG];
    #pragma unroll
    for (int k = 0; k < NG; ++k) {
        int e    = k * NTHREADS + tid;
        int sl   = e / NCOLS;
        col_k[k] = e - sl * NCOLS;
        int slot = slice_lo + sl;
        ok_k[k]  = (e < SLOTS * NCOLS) && (slot < cnt);
        src_k[k] = ok_k[k] ? s_order[slot] : 0;
    }
    float v_k[NG];
    #pragma unroll
    for (int k = 0; k < NG; ++k)
        v_k[k] = ok_k[k] ? __ldg(&bpred[(long long)src_k[k] * NCOLS + col_k[k]]) : 0.0f;
    #pragma unroll
    for (int k = 0; k < NG; ++k) {
        int e = k * NTHREADS + tid;
        if (e < SLOTS * NCOLS) bout[e] = v_k[k];
    }
}

extern "C" void kernel_launch(void* const* d_in, const int* in_sizes, int n_in,
                              void* d_out, int out_size)
{
    const float* pred = (const float*)d_in[0];
    float* out = (float*)d_out;
    compact_kernel<<<BATCH * SLICES, NTHREADS>>>(pred, out);
}

// round 5
// speedup vs baseline: 1.3462x; 1.0385x over previous
#include <cuda_runtime.h>

#define BATCH    16
#define NROWS    25200
#define NCOLS    85
#define MAXDET   300
#define CTHRES   0.25f
#define NTHREADS 512
#define NWARPS   (NTHREADS / 32)   // 16
#define NSLICES  9
#define NGMAX    11                // ceil(66*85 / 512)

// Balanced slice boundaries: early slices own many slots (short scans),
// late slices few slots (long scans). cost ~ scan_rows + 6*slots equalized.
__device__ __constant__ int d_clo[NSLICES] = {0, 66, 119, 163, 199, 228, 252, 272, 288};
__device__ __constant__ int d_chi[NSLICES] = {66, 119, 163, 199, 228, 252, 272, 288, 300};
// Scan bound per slice: P(count(U) < c_hi) negligible (>=5 sigma), fallback loop
// below preserves correctness regardless.
__device__ __constant__ int d_u[NSLICES]   = {160, 256, 320, 352, 416, 448, 480, 480, 512};

__global__ __launch_bounds__(NTHREADS, 2)
void compact_kernel(const float* __restrict__ pred, float* __restrict__ out)
{
    __shared__ int s_order[MAXDET];
    __shared__ int s_cnt[NWARPS];
    __shared__ int s_off[NWARPS];
    __shared__ int s_total;

    const int b     = blockIdx.x / NSLICES;
    const int slice = blockIdx.x % NSLICES;
    const int tid   = threadIdx.x;
    const int lane  = tid & 31;
    const int warp  = tid >> 5;

    const int lo = d_clo[slice];
    const int hi = d_chi[slice];
    const int u  = d_u[slice];
    const unsigned lanemask = (1u << lane) - 1u;

    const float* bpred = pred + (long long)b * NROWS * NCOLS;

    int base = 0;

    // ---- chunk 1: rows [0, u) — expected to be the ONLY chunk ----
    {
        bool m = false;
        if (tid < u)
            m = __ldg(&bpred[(long long)tid * NCOLS + 4]) > CTHRES;

        unsigned bal = __ballot_sync(0xffffffffu, m);
        if (lane == 0) s_cnt[warp] = __popc(bal);
        __syncthreads();
        if (warp == 0) {
            int v = (lane < NWARPS) ? s_cnt[lane] : 0;
            int inc = v;
            #pragma unroll
            for (int o = 1; o < 32; o <<= 1) {
                int t = __shfl_up_sync(0xffffffffu, inc, o);
                if (lane >= o) inc += t;
            }
            if (lane < NWARPS) s_off[lane] = inc - v;
            if (lane == 31) s_total = inc;
        }
        __syncthreads();
        if (m) {
            int rank = s_off[warp] + __popc(bal & lanemask);
            if (rank < MAXDET) s_order[rank] = tid;
        }
        base = s_total;
    }

    // ---- fallback: only if chunk 1 didn't reach this slice's upper rank ----
    int row0 = u;
    while (base < hi && row0 < NROWS) {
        __syncthreads();   // order s_total read above vs rewrite below
        int i = row0 + tid;
        bool m = false;
        if (i < NROWS)
            m = __ldg(&bpred[(long long)i * NCOLS + 4]) > CTHRES;

        unsigned bal = __ballot_sync(0xffffffffu, m);
        if (lane == 0) s_cnt[warp] = __popc(bal);
        __syncthreads();
        if (warp == 0) {
            int v = (lane < NWARPS) ? s_cnt[lane] : 0;
            int inc = v;
            #pragma unroll
            for (int o = 1; o < 32; o <<= 1) {
                int t = __shfl_up_sync(0xffffffffu, inc, o);
                if (lane >= o) inc += t;
            }
            if (lane < NWARPS) s_off[lane] = inc - v;
            if (lane == 31) s_total = inc;
        }
        __syncthreads();
        if (m) {
            int rank = base + s_off[warp] + __popc(bal & lanemask);
            if (rank < MAXDET) s_order[rank] = i;
        }
        base += s_total;
        row0 += NTHREADS;
    }
    __syncthreads();   // s_order visible to all warps

    int cnt = base;
    if (cnt > MAXDET) cnt = MAXDET;

    const int nelem = (hi - lo) * NCOLS;
    float* bout = out + (long long)b * MAXDET * NCOLS + (long long)lo * NCOLS;

    // Gather slots [lo, hi): batched so loads are independent (MLP up to 11).
    int  src_k[NGMAX];
    int  col_k[NGMAX];
    bool ok_k[NGMAX];
    #pragma unroll
    for (int k = 0; k < NGMAX; ++k) {
        int e    = k * NTHREADS + tid;
        int sl   = e / NCOLS;
        col_k[k] = e - sl * NCOLS;
        int slot = lo + sl;
        ok_k[k]  = (e < nelem) && (slot < cnt);
        src_k[k] = ok_k[k] ? s_order[slot] : 0;
    }
    float v_k[NGMAX];
    #pragma unroll
    for (int k = 0; k < NGMAX; ++k)
        v_k[k] = ok_k[k] ? __ldg(&bpred[(long long)src_k[k] * NCOLS + col_k[k]]) : 0.0f;
    #pragma unroll
    for (int k = 0; k < NGMAX; ++k) {
        int e = k * NTHREADS + tid;
        if (e < nelem) bout[e] = v_k[k];
    }
}

extern "C" void kernel_launch(void* const* d_in, const int* in_sizes, int n_in,
                              void* d_out, int out_size)
{
    const float* pred = (const float*)d_in[0];
    float* out = (float*)d_out;
    compact_kernel<<<BATCH * NSLICES, NTHREADS>>>(pred, out);
}

// round 6
// speedup vs baseline: 1.3527x; 1.0048x over previous
#include <cuda_runtime.h>

#define BATCH    16
#define NROWS    25200
#define NCOLS    85
#define MAXDET   300
#define CTHRES   0.25f
#define NTHREADS 512
#define NWARPS   (NTHREADS / 32)   // 16
#define NSLICES  9
#define NGMAX    11                // ceil(66*85 / 512)

// Balanced slice boundaries: early slices own many slots (short scans),
// late slices few slots (long scans).
__device__ __constant__ int d_clo[NSLICES] = {0, 66, 119, 163, 199, 228, 252, 272, 288};
__device__ __constant__ int d_chi[NSLICES] = {66, 119, 163, 199, 228, 252, 272, 288, 300};
// Scan bound per slice: P(count(u) < c_hi) negligible (>=5 sigma); the
// fallback loop preserves correctness for arbitrary data regardless.
__device__ __constant__ int d_u[NSLICES]   = {160, 256, 320, 352, 416, 448, 480, 480, 512};

__global__ __launch_bounds__(NTHREADS, 2)
void compact_kernel(const float* __restrict__ pred, float* __restrict__ out)
{
    __shared__ int s_order[MAXDET];
    __shared__ int s_cnt[NWARPS];

    const int b     = blockIdx.x / NSLICES;
    const int slice = blockIdx.x % NSLICES;
    const int tid   = threadIdx.x;
    const int lane  = tid & 31;
    const int warp  = tid >> 5;

    const int lo = d_clo[slice];
    const int hi = d_chi[slice];
    const int u  = d_u[slice];
    const unsigned lanemask = (1u << lane) - 1u;

    const float* bpred = pred + (long long)b * NROWS * NCOLS;

    int base;

    // ---- chunk 1: rows [0, u) — expected to be the ONLY chunk ----
    {
        bool m = false;
        if (tid < u)
            m = __ldg(&bpred[(long long)tid * NCOLS + 4]) > CTHRES;

        unsigned bal = __ballot_sync(0xffffffffu, m);
        if (lane == 0) s_cnt[warp] = __popc(bal);
        __syncthreads();                        // barrier #1 (only one in scan)

        // Every warp redundantly scans the 16 warp counts — no 2nd barrier.
        int v = (lane < NWARPS) ? s_cnt[lane] : 0;
        int inc = v;
        #pragma unroll
        for (int o = 1; o < NWARPS; o <<= 1) {
            int t = __shfl_up_sync(0xffffffffu, inc, o);
            if (lane >= o) inc += t;
        }
        int total = __shfl_sync(0xffffffffu, inc, NWARPS - 1);
        int wpre  = (warp == 0) ? 0 : __shfl_sync(0xffffffffu, inc, warp - 1);

        if (m) {
            int rank = wpre + __popc(bal & lanemask);
            if (rank < MAXDET) s_order[rank] = tid;
        }
        base = total;
    }

    // ---- fallback: only if chunk 1 didn't cover this slice (statistically never) ----
    int row0 = u;
    while (base < hi && row0 < NROWS) {
        __syncthreads();    // protect s_cnt rewrite vs prior reads
        int i = row0 + tid;
        bool m = false;
        if (i < NROWS)
            m = __ldg(&bpred[(long long)i * NCOLS + 4]) > CTHRES;

        unsigned bal = __ballot_sync(0xffffffffu, m);
        if (lane == 0) s_cnt[warp] = __popc(bal);
        __syncthreads();

        int v = (lane < NWARPS) ? s_cnt[lane] : 0;
        int inc = v;
        #pragma unroll
        for (int o = 1; o < NWARPS; o <<= 1) {
            int t = __shfl_up_sync(0xffffffffu, inc, o);
            if (lane >= o) inc += t;
        }
        int total = __shfl_sync(0xffffffffu, inc, NWARPS - 1);
        int wpre  = (warp == 0) ? 0 : __shfl_sync(0xffffffffu, inc, warp - 1);

        if (m) {
            int rank = base + wpre + __popc(bal & lanemask);
            if (rank < MAXDET) s_order[rank] = i;
        }
        base += total;
        row0 += NTHREADS;
    }
    __syncthreads();        // barrier #2: s_order visible to all warps

    int cnt = base;
    if (cnt > MAXDET) cnt = MAXDET;

    const int nslots = hi - lo;
    const int nelem  = nslots * NCOLS;
    float* bout = out + (long long)b * MAXDET * NCOLS + (long long)lo * NCOLS;

    // Gather slots [lo, hi). Division-free: one initial div, then incremental
    // (sl, col) update per step (NTHREADS = 6*NCOLS + 2).
    int sl  = tid / NCOLS;      // 0..6
    int col = tid - sl * NCOLS;

    int  src_k[NGMAX];
    int  col_k[NGMAX];
    bool ok_k[NGMAX];
    {
        int sl_i = sl, col_i = col;
        #pragma unroll
        for (int k = 0; k < NGMAX; ++k) {
            int slot = lo + sl_i;
            ok_k[k]  = (sl_i < nslots) && (slot < cnt);
            col_k[k] = col_i;
            src_k[k] = ok_k[k] ? s_order[slot] : 0;
            // advance by NTHREADS elements: += (6 rows, 2 cols)
            sl_i  += 6;
            col_i += 2;
            if (col_i >= NCOLS) { col_i -= NCOLS; sl_i += 1; }
        }
    }
    float v_k[NGMAX];
    #pragma unroll
    for (int k = 0; k < NGMAX; ++k)
        v_k[k] = ok_k[k] ? __ldg(&bpred[(long long)src_k[k] * NCOLS + col_k[k]]) : 0.0f;

    {
        int sl_i = sl, col_i = col;
        int e = tid;
        #pragma unroll
        for (int k = 0; k < NGMAX; ++k) {
            if (sl_i < nslots) bout[e] = v_k[k];
            e     += NTHREADS;
            sl_i  += 6;
            col_i += 2;
            if (col_i >= NCOLS) { col_i -= NCOLS; sl_i += 1; }
        }
    }
}

extern "C" void kernel_launch(void* const* d_in, const int* in_sizes, int n_in,
                              void* d_out, int out_size)
{
    const float* pred = (const float*)d_in[0];
    float* out = (float*)d_out;
    compact_kernel<<<BATCH * NSLICES, NTHREADS>>>(pred, out);
}